// round 1
// baseline (speedup 1.0000x reference)
#include <cuda_runtime.h>
#include <cstdint>

#define H_CH 256
#define NST  64
#define LL   4096
#define NBATCH 16

// Scratch (device globals: allocation-free rule)
__device__ float2 g_Kf[H_CH * LL];     // raw S4 kernel spectrum
__device__ float2 g_Khat[H_CH * LL];   // hermitian part, pre-scaled by 1/L

__device__ __forceinline__ float2 cmul(float2 a, float2 b) {
    return make_float2(a.x * b.x - a.y * b.y, a.x * b.y + a.y * b.x);
}

// Correctly-rounded float sin/cos via double polynomial.
// Needed so 1+cos / 1-cos cancellation sites match the float32 reference bitwise.
// Valid for ang in [-2*pi, 0].
__device__ __forceinline__ void sincos_acc(float angf, float* s, float* c) {
    double x  = (double)angf;
    double kd = rint(x * 0.63661977236758134308);   // x / (pi/2)
    double r  = x - kd * 1.5707963267948966;
    r        -= kd * 6.123233995736766e-17;
    int q = (int)kd;
    double r2 = r * r;
    double sr = r * (1.0 + r2 * (-1.6666666666666666e-01 + r2 * (8.3333333333333332e-03
                 + r2 * (-1.9841269841269841e-04 + r2 * 2.7557319223985893e-06))));
    double cr = 1.0 + r2 * (-0.5 + r2 * (4.1666666666666664e-02
                 + r2 * (-1.3888888888888889e-03 + r2 * (2.4801587301587302e-05
                 - r2 * 2.7557319223985888e-07))));
    double ss, cc;
    switch (q & 3) {
        case 0:  ss =  sr; cc =  cr; break;
        case 1:  ss =  cr; cc = -sr; break;
        case 2:  ss = -sr; cc = -cr; break;
        default: ss = -cr; cc =  sr; break;
    }
    *s = (float)ss;
    *c = (float)cc;
}

// ---------------------------------------------------------------------------
// Kernel 1: S4 DPLR frequency-domain kernel at the L roots of unity.
// grid = H*8 blocks of 256 threads; each block covers 512 consecutive l.
// ---------------------------------------------------------------------------
__global__ void kgen(const float* __restrict__ Lre, const float* __restrict__ Lim,
                     const float* __restrict__ Pre, const float* __restrict__ Pim,
                     const float* __restrict__ Bre, const float* __restrict__ Bim,
                     const float* __restrict__ Cre, const float* __restrict__ Cim,
                     const float* __restrict__ lstep) {
    __shared__ float2 sLam[NST], sCB[NST], sCP[NST], sPB[NST], sPP[NST];
    __shared__ float  s_tos;
    int h   = blockIdx.x >> 3;
    int seg = blockIdx.x & 7;
    int tid = threadIdx.x;

    if (tid < NST) {
        int idx = h * NST + tid;
        float lr = Lre[idx], li = Lim[idx];
        float pr = Pre[idx], pi = Pim[idx];
        float br = Bre[idx], bi = Bim[idx];
        float cr = Cre[idx], ci = Cim[idx];
        sLam[tid] = make_float2(lr, li);
        // conj(C)*B, conj(C)*P, conj(P)*B, conj(P)*P
        sCB[tid] = make_float2(cr * br + ci * bi, cr * bi - ci * br);
        sCP[tid] = make_float2(cr * pr + ci * pi, cr * pi - ci * pr);
        sPB[tid] = make_float2(pr * br + pi * bi, pr * bi - pi * br);
        sPP[tid] = make_float2(pr * pr + pi * pi, 0.0f);
    }
    if (tid == 0) s_tos = 2.0f / __expf(lstep[h]);
    __syncthreads();
    float tos = s_tos;

    const float neg2pi = (float)(-6.283185307179586);

    #pragma unroll
    for (int ii = 0; ii < 2; ++ii) {
        int l = seg * 512 + ii * 256 + tid;
        float ang = neg2pi * ((float)l * (1.0f / 4096.0f));
        float so, co;
        sincos_acc(ang, &so, &co);

        float opr = 1.0f + co, opi = so;     // 1 + Omega   (exact subtraction sites)
        float omr = 1.0f - co, omi = -so;    // 1 - Omega
        float rinv = __fdividef(1.0f, opr * opr + opi * opi);
        float cr_ = 2.0f * opr * rinv;
        float ci_ = -2.0f * opi * rinv;      // c = 2/(1+Omega)
        float gr = tos * ((omr * opr + omi * opi) * rinv);
        float gi = tos * ((omi * opr - omr * opi) * rinv);  // g = (2/step)(1-O)/(1+O)

        float a00r = 0.f, a00i = 0.f, a01r = 0.f, a01i = 0.f;
        float a10r = 0.f, a10i = 0.f, a11r = 0.f, a11i = 0.f;
        #pragma unroll 8
        for (int n = 0; n < NST; ++n) {
            float2 lam = sLam[n];
            float dr = gr - lam.x, di = gi - lam.y;
            float inv = __fdividef(1.0f, dr * dr + di * di);
            float ir = dr * inv, iq = -di * inv;   // 1/(g - Lambda_n)
            float2 v;
            v = sCB[n]; a00r += v.x * ir - v.y * iq; a00i += v.x * iq + v.y * ir;
            v = sCP[n]; a01r += v.x * ir - v.y * iq; a01i += v.x * iq + v.y * ir;
            v = sPB[n]; a10r += v.x * ir - v.y * iq; a10i += v.x * iq + v.y * ir;
            v = sPP[n]; a11r += v.x * ir;            a11i += v.x * iq;
        }
        // K = c * (k00 - k01 * k10 / (1 + k11))
        float tr = 1.0f + a11r, ti = a11i;
        float tinv = __fdividef(1.0f, tr * tr + ti * ti);
        float mr = a01r * a10r - a01i * a10i;
        float mi = a01r * a10i + a01i * a10r;
        float qr = (mr * tr + mi * ti) * tinv;
        float qi = (mi * tr - mr * ti) * tinv;
        float kr = a00r - qr, ki = a00i - qi;
        g_Kf[h * LL + l] = make_float2(cr_ * kr - ci_ * ki, cr_ * ki + ci_ * kr);
    }
}

// ---------------------------------------------------------------------------
// Kernel 2: Khat[k] = 0.5*(K[k] + conj(K[-k])) / L
// (Hermitian part of K: makes "take real part of ifft" exact, enabling
//  2-batch complex packing in the conv kernel.)
// ---------------------------------------------------------------------------
__global__ void khat_kernel() {
    int idx = blockIdx.x * blockDim.x + threadIdx.x;
    if (idx >= H_CH * LL) return;
    int h = idx >> 12;
    int l = idx & 4095;
    int lr = (LL - l) & 4095;
    float2 k1 = g_Kf[(h << 12) + l];
    float2 k2 = g_Kf[(h << 12) + lr];
    const float sc = 0.5f / 4096.0f;
    g_Khat[idx] = make_float2((k1.x + k2.x) * sc, (k1.y - k2.y) * sc);
}

// ---------------------------------------------------------------------------
// Kernel 3: packed FFT convolution.
// One CTA per (batch-pair, h): z = u0 + i*u1 -> FFT -> *Khat -> IFFT ->
// y0 = Re, y1 = Im.  Radix-4 Stockham, 6 stages, ping-pong shared buffers.
// ---------------------------------------------------------------------------
#define SWX(i) ((i) + ((i) >> 2))   // pad swizzle: breaks stride-4/16 bank conflicts
#define NPAD 5120                   // 4095 + 1023 + 1 rounded up

template <int DIR>
__device__ __forceinline__ void fft_stages(float2* A, float2* Bf, int tid) {
    float2* X = A;
    float2* Y = Bf;
    #pragma unroll
    for (int k = 0; k < 6; ++k) {
        const int twok = 2 * k;
        const int s = 1 << twok;
        const int n = LL >> twok;
        const float base = (float)DIR * 6.2831853071795864f / (float)n;
        #pragma unroll
        for (int it = 0; it < 2; ++it) {
            int j = tid + it * 512;              // butterfly index, 0..1023
            float2 a = X[SWX(j)];
            float2 b = X[SWX(j + 1024)];
            float2 c = X[SWX(j + 2048)];
            float2 d = X[SWX(j + 3072)];
            int p = j >> twok;
            float ang = base * (float)p;         // |ang| < pi/2 -> fast path
            float sn, cs;
            __sincosf(ang, &sn, &cs);
            float2 w1 = make_float2(cs, sn);
            float2 w2 = cmul(w1, w1);
            float2 w3 = cmul(w2, w1);
            float2 apc = make_float2(a.x + c.x, a.y + c.y);
            float2 amc = make_float2(a.x - c.x, a.y - c.y);
            float2 bpd = make_float2(b.x + d.x, b.y + d.y);
            float2 bmd = make_float2(b.x - d.x, b.y - d.y);
            // i*DIR*(b-d)
            float2 tib = make_float2(-(float)DIR * bmd.y, (float)DIR * bmd.x);
            float2 o0 = make_float2(apc.x + bpd.x, apc.y + bpd.y);
            float2 o1 = cmul(make_float2(amc.x + tib.x, amc.y + tib.y), w1);
            float2 o2 = cmul(make_float2(apc.x - bpd.x, apc.y - bpd.y), w2);
            float2 o3 = cmul(make_float2(amc.x - tib.x, amc.y - tib.y), w3);
            int wb = j + 3 * (p << twok);        // q + 4*s*p
            Y[SWX(wb)]         = o0;
            Y[SWX(wb + s)]     = o1;
            Y[SWX(wb + 2 * s)] = o2;
            Y[SWX(wb + 3 * s)] = o3;
        }
        __syncthreads();
        float2* t = X; X = Y; Y = t;
    }
    // 6 stages (even) -> result back in A
}

__global__ void fftconv(const float* __restrict__ u, float* __restrict__ y) {
    extern __shared__ float2 smem[];
    float2* A  = smem;
    float2* Bf = smem + NPAD;
    int tid = threadIdx.x;
    int h  = blockIdx.x & 255;
    int pb = blockIdx.x >> 8;

    size_t off0 = ((size_t)(2 * pb) * H_CH + (size_t)h) * LL;
    const float* u0 = u + off0;
    const float* u1 = u0 + (size_t)H_CH * LL;

    #pragma unroll
    for (int it = 0; it < 8; ++it) {
        int i = tid + it * 512;
        A[SWX(i)] = make_float2(u0[i], u1[i]);
    }
    __syncthreads();

    fft_stages<-1>(A, Bf, tid);                 // forward FFT of packed row

    const float2* Kh = g_Khat + ((size_t)h << 12);
    #pragma unroll
    for (int it = 0; it < 8; ++it) {
        int i = tid + it * 512;
        A[SWX(i)] = cmul(A[SWX(i)], Kh[i]);     // spectral multiply (incl. 1/L)
    }
    __syncthreads();

    fft_stages<1>(A, Bf, tid);                  // inverse FFT (no extra scale)

    float* y0 = y + off0;
    float* y1 = y0 + (size_t)H_CH * LL;
    #pragma unroll
    for (int it = 0; it < 8; ++it) {
        int i = tid + it * 512;
        float2 z = A[SWX(i)];
        y0[i] = z.x;
        y1[i] = z.y;
    }
}

// ---------------------------------------------------------------------------
extern "C" void kernel_launch(void* const* d_in, const int* in_sizes, int n_in,
                              void* d_out, int out_size) {
    (void)in_sizes; (void)n_in; (void)out_size;
    const float* u   = (const float*)d_in[0];
    const float* Lre = (const float*)d_in[1];
    const float* Lim = (const float*)d_in[2];
    const float* Pre = (const float*)d_in[3];
    const float* Pim = (const float*)d_in[4];
    const float* Bre = (const float*)d_in[5];
    const float* Bim = (const float*)d_in[6];
    const float* Cre = (const float*)d_in[7];
    const float* Cim = (const float*)d_in[8];
    const float* lst = (const float*)d_in[9];
    float* y = (float*)d_out;

    const int smem_bytes = 2 * NPAD * (int)sizeof(float2);  // 81920
    cudaFuncSetAttribute(fftconv, cudaFuncAttributeMaxDynamicSharedMemorySize, smem_bytes);

    kgen<<<H_CH * 8, 256>>>(Lre, Lim, Pre, Pim, Bre, Bim, Cre, Cim, lst);
    khat_kernel<<<(H_CH * LL + 255) / 256, 256>>>();
    fftconv<<<(NBATCH / 2) * H_CH, 512, smem_bytes>>>(u, y);
}

// round 6
// speedup vs baseline: 1.3849x; 1.3849x over previous
#include <cuda_runtime.h>
#include <cstdint>

#define H_CH 256
#define NST  64
#define LL   4096
#define NBATCH 16

typedef unsigned long long ull;

// Scratch (device global: allocation-free rule)
__device__ float2 g_Khat[H_CH * LL];   // hermitian part of K, pre-scaled by 1/L

__device__ __forceinline__ float2 cmul(float2 a, float2 b) {
    return make_float2(a.x * b.x - a.y * b.y, a.x * b.y + a.y * b.x);
}
__device__ __forceinline__ float2 cadd(float2 a, float2 b) {
    return make_float2(a.x + b.x, a.y + b.y);
}
__device__ __forceinline__ float2 csub(float2 a, float2 b) {
    return make_float2(a.x - b.x, a.y - b.y);
}

// ---- packed f32x2 helpers ----
__device__ __forceinline__ ull pk(float lo, float hi) {
    ull r; asm("mov.b64 %0,{%1,%2};" : "=l"(r) : "f"(lo), "f"(hi)); return r;
}
__device__ __forceinline__ void upk(ull v, float& lo, float& hi) {
    asm("mov.b64 {%0,%1},%2;" : "=f"(lo), "=f"(hi) : "l"(v));
}
__device__ __forceinline__ ull fma2(ull a, ull b, ull c) {
    ull d; asm("fma.rn.f32x2 %0,%1,%2,%3;" : "=l"(d) : "l"(a), "l"(b), "l"(c)); return d;
}
__device__ __forceinline__ ull add2(ull a, ull b) {
    ull d; asm("add.rn.f32x2 %0,%1,%2;" : "=l"(d) : "l"(a), "l"(b)); return d;
}
__device__ __forceinline__ ull mul2(ull a, ull b) {
    ull d; asm("mul.rn.f32x2 %0,%1,%2;" : "=l"(d) : "l"(a), "l"(b)); return d;
}

// Correctly-rounded float sin/cos via double polynomial.
// Needed so 1+cos / 1-cos cancellation sites match the float32 reference bitwise.
// Valid for ang in [-2*pi, 0].
__device__ __forceinline__ void sincos_acc(float angf, float* s, float* c) {
    double x  = (double)angf;
    double kd = rint(x * 0.63661977236758134308);   // x / (pi/2)
    double r  = x - kd * 1.5707963267948966;
    r        -= kd * 6.123233995736766e-17;
    int q = (int)kd;
    double r2 = r * r;
    double sr = r * (1.0 + r2 * (-1.6666666666666666e-01 + r2 * (8.3333333333333332e-03
                 + r2 * (-1.9841269841269841e-04 + r2 * 2.7557319223985893e-06))));
    double cr = 1.0 + r2 * (-0.5 + r2 * (4.1666666666666664e-02
                 + r2 * (-1.3888888888888889e-03 + r2 * (2.4801587301587302e-05
                 - r2 * 2.7557319223985888e-07))));
    double ss, cc;
    switch (q & 3) {
        case 0:  ss =  sr; cc =  cr; break;
        case 1:  ss =  cr; cc = -sr; break;
        case 2:  ss = -sr; cc = -cr; break;
        default: ss = -cr; cc =  sr; break;
    }
    *s = (float)ss;
    *c = (float)cc;
}

// ---------------------------------------------------------------------------
// Kernel 1: S4 DPLR frequency-domain kernel + FUSED Hermitian part.
// grid = H*8 blocks of 256 threads. Each thread handles the MIRROR PAIR
// (gid, 4096-gid) inside ONE n-loop (gid=0 handles the self-mirrored bins
// 0 and 2048), so Khat[l] = (K[l]+conj(K[-l]))/(2L) is computed in-register
// with no K round trip through HBM. Packed f32x2 FMAs in the Cauchy loop.
// ---------------------------------------------------------------------------
__global__ __launch_bounds__(256)
void kgen(const float* __restrict__ Lre, const float* __restrict__ Lim,
          const float* __restrict__ Pre, const float* __restrict__ Pim,
          const float* __restrict__ Bre, const float* __restrict__ Bim,
          const float* __restrict__ Cre, const float* __restrict__ Cim,
          const float* __restrict__ lstep) {
    __shared__ float4 sA[NST];  // (-lam.re, -lam.im, |P|^2, |P|^2)
    __shared__ float4 sB[NST];  // (cb.x, cb.y, -cb.y, cb.x)   cb = conj(C)*B
    __shared__ float4 sC[NST];  // conj(C)*P
    __shared__ float4 sD[NST];  // conj(P)*B
    __shared__ float  s_tos;

    int h   = blockIdx.x >> 3;
    int seg = blockIdx.x & 7;
    int tid = threadIdx.x;

    if (tid < NST) {
        int idx = h * NST + tid;
        float lr = Lre[idx], li = Lim[idx];
        float pr = Pre[idx], pi = Pim[idx];
        float br = Bre[idx], bi = Bim[idx];
        float cr = Cre[idx], ci = Cim[idx];
        float cbx = cr * br + ci * bi, cby = cr * bi - ci * br;
        float cpx = cr * pr + ci * pi, cpy = cr * pi - ci * pr;
        float pbx = pr * br + pi * bi, pby = pr * bi - pi * br;
        float pp  = pr * pr + pi * pi;
        sA[tid] = make_float4(-lr, -li, pp, pp);
        sB[tid] = make_float4(cbx, cby, -cby, cbx);
        sC[tid] = make_float4(cpx, cpy, -cpy, cpx);
        sD[tid] = make_float4(pbx, pby, -pby, pbx);
    }
    if (tid == 0) s_tos = 2.0f / __expf(lstep[h]);
    __syncthreads();
    float tos = s_tos;

    const float neg2pi = (float)(-6.283185307179586);

    // mirror-pair l mapping: (gid, 4096-gid); gid==0 -> (0, 2048)
    int gid = seg * 256 + tid;          // 0..2047 per h
    int lv[2];
    lv[0] = gid;
    lv[1] = (gid == 0) ? 2048 : (LL - gid);
    bool selfm = (gid == 0);            // both bins self-mirrored

    float crv[2], civ[2];               // c = 2/(1+Omega)
    ull   gpk[2];
    #pragma unroll
    for (int ii = 0; ii < 2; ++ii) {
        int l = lv[ii];
        float ang = neg2pi * ((float)l * (1.0f / 4096.0f));
        float so, co;
        sincos_acc(ang, &so, &co);
        float opr = 1.0f + co, opi = so;     // 1 + Omega (exact subtraction sites)
        float omr = 1.0f - co, omi = -so;    // 1 - Omega
        float rinv = __fdividef(1.0f, opr * opr + opi * opi);
        crv[ii] =  2.0f * opr * rinv;
        civ[ii] = -2.0f * opi * rinv;
        float gr = tos * ((omr * opr + omi * opi) * rinv);
        float gi = tos * ((omi * opr - omr * opi) * rinv);
        gpk[ii] = pk(gr, gi);
    }

    ull a00[2] = {0ull, 0ull}, a01[2] = {0ull, 0ull};
    ull a10[2] = {0ull, 0ull}, a11[2] = {0ull, 0ull};

    #pragma unroll 8
    for (int n = 0; n < NST; ++n) {
        float4 fa = sA[n], fb = sB[n], fc = sC[n], fd = sD[n];
        ull nlam = pk(fa.x, fa.y);
        ull pp2  = pk(fa.z, fa.w);
        ull bxy  = pk(fb.x, fb.y), bzw = pk(fb.z, fb.w);
        ull cxy  = pk(fc.x, fc.y), czw = pk(fc.z, fc.w);
        ull dxy  = pk(fd.x, fd.y), dzw = pk(fd.z, fd.w);
        #pragma unroll
        for (int ii = 0; ii < 2; ++ii) {
            ull d = add2(gpk[ii], nlam);         // g - lambda
            float dr, di; upk(d, dr, di);
            float inv = __fdividef(1.0f, fmaf(dr, dr, di * di));
            ull iriq = mul2(d, pk(inv, -inv));   // (ir, iq) = 1/(g-lam)
            float ir, iq; upk(iriq, ir, iq);
            ull irir = pk(ir, ir), iqiq = pk(iq, iq);
            a00[ii] = fma2(bxy, irir, a00[ii]); a00[ii] = fma2(bzw, iqiq, a00[ii]);
            a01[ii] = fma2(cxy, irir, a01[ii]); a01[ii] = fma2(czw, iqiq, a01[ii]);
            a10[ii] = fma2(dxy, irir, a10[ii]); a10[ii] = fma2(dzw, iqiq, a10[ii]);
            a11[ii] = fma2(pp2, iriq, a11[ii]);
        }
    }

    float2 kout[2];
    #pragma unroll
    for (int ii = 0; ii < 2; ++ii) {
        float a00r, a00i, a01r, a01i, a10r, a10i, a11r, a11i;
        upk(a00[ii], a00r, a00i); upk(a01[ii], a01r, a01i);
        upk(a10[ii], a10r, a10i); upk(a11[ii], a11r, a11i);
        // K = c * (k00 - k01 * k10 / (1 + k11))
        float tr = 1.0f + a11r, ti = a11i;
        float tinv = __fdividef(1.0f, tr * tr + ti * ti);
        float mr = a01r * a10r - a01i * a10i;
        float mi = a01r * a10i + a01i * a10r;
        float qr = (mr * tr + mi * ti) * tinv;
        float qi = (mi * tr - mr * ti) * tinv;
        float kr = a00r - qr, ki = a00i - qi;
        float cr_ = crv[ii], ci_ = civ[ii];
        kout[ii] = make_float2(cr_ * kr - ci_ * ki, cr_ * ki + ci_ * kr);
    }

    // Fused Hermitian part: Khat[l] = (K[l] + conj(K[-l])) * 0.5/L
    const float sc = 0.5f / 4096.0f;
    float2* Kh = g_Khat + ((size_t)h << 12);
    if (selfm) {
        Kh[lv[0]] = make_float2(2.0f * kout[0].x * sc, 0.0f);
        Kh[lv[1]] = make_float2(2.0f * kout[1].x * sc, 0.0f);
    } else {
        Kh[lv[0]] = make_float2((kout[0].x + kout[1].x) * sc,
                                (kout[0].y - kout[1].y) * sc);
        Kh[lv[1]] = make_float2((kout[1].x + kout[0].x) * sc,
                                (kout[1].y - kout[0].y) * sc);
    }
}

// ---------------------------------------------------------------------------
// Kernel 2: packed FFT convolution, radix-8 Stockham (4096 = 8^4, 4 stages).
// One CTA (512 threads) per (batch-pair, h): z = u0 + i*u1 -> FFT -> *Khat
// -> IFFT -> y0 = Re, y1 = Im. (Exact because Khat is the Hermitian part.)
// ---------------------------------------------------------------------------
#define SW8(i) ((i) + ((i) >> 3))   // pad swizzle for radix-8 access patterns
#define NPAD 4608                   // 4096 + 512

template <int DIR>
__device__ __forceinline__ void fft8stages(float2* A, float2* Bf, int j) {
    float2* X = A;
    float2* Y = Bf;
    const float D = (float)DIR;
    #pragma unroll
    for (int k = 0; k < 4; ++k) {
        const int s = 1 << (3 * k);
        float2 x[8];
        #pragma unroll
        for (int r = 0; r < 8; ++r) x[r] = X[SW8(j + 512 * r)];

        int p = j >> (3 * k);
        int q = j & (s - 1);

        // DFT8 = radix-2 over two DFT4s (DIT)
        float2 t0 = cadd(x[0], x[4]), t1 = csub(x[0], x[4]);
        float2 t2 = cadd(x[2], x[6]);
        float2 d26 = csub(x[2], x[6]);
        float2 t3 = make_float2(-D * d26.y, D * d26.x);
        float2 e0 = cadd(t0, t2), e1 = cadd(t1, t3);
        float2 e2 = csub(t0, t2), e3 = csub(t1, t3);

        float2 u0 = cadd(x[1], x[5]), u1 = csub(x[1], x[5]);
        float2 u2 = cadd(x[3], x[7]);
        float2 d37 = csub(x[3], x[7]);
        float2 u3 = make_float2(-D * d37.y, D * d37.x);
        float2 o0 = cadd(u0, u2), o1 = cadd(u1, u3);
        float2 o2 = csub(u0, u2), o3 = csub(u1, u3);

        const float C8 = 0.70710678118654752f;
        // o1 *= w8^D ; o2 *= i*D ; o3 *= w8^(3D)
        float2 q1 = make_float2(C8 * (o1.x - D * o1.y), C8 * (D * o1.x + o1.y));
        float2 q2 = make_float2(-D * o2.y, D * o2.x);
        float2 q3 = make_float2(C8 * (-o3.x - D * o3.y), C8 * (D * o3.x - o3.y));

        float2 out[8];
        out[0] = cadd(e0, o0); out[4] = csub(e0, o0);
        out[1] = cadd(e1, q1); out[5] = csub(e1, q1);
        out[2] = cadd(e2, q2); out[6] = csub(e2, q2);
        out[3] = cadd(e3, q3); out[7] = csub(e3, q3);

        if (k < 3) {
            const float base = D * 6.2831853071795864f / (float)(4096 >> (3 * k));
            float sn, cs;
            __sincosf(base * (float)p, &sn, &cs);
            float2 w1 = make_float2(cs, sn);
            float2 w2 = cmul(w1, w1);
            float2 w3 = cmul(w2, w1);
            float2 w4 = cmul(w2, w2);
            float2 w5 = cmul(w3, w2);
            float2 w6 = cmul(w3, w3);
            float2 w7 = cmul(w4, w3);
            out[1] = cmul(out[1], w1); out[2] = cmul(out[2], w2);
            out[3] = cmul(out[3], w3); out[4] = cmul(out[4], w4);
            out[5] = cmul(out[5], w5); out[6] = cmul(out[6], w6);
            out[7] = cmul(out[7], w7);
        }

        int wb = q + 8 * s * p;
        #pragma unroll
        for (int r = 0; r < 8; ++r) Y[SW8(wb + s * r)] = out[r];
        __syncthreads();
        float2* t = X; X = Y; Y = t;
    }
    // 4 stages (even) -> result back in A
}

__global__ __launch_bounds__(512, 2)
void fftconv(const float* __restrict__ u, float* __restrict__ y) {
    extern __shared__ float2 smem[];
    float2* A  = smem;
    float2* Bf = smem + NPAD;
    int tid = threadIdx.x;
    int h  = blockIdx.x & 255;
    int pb = blockIdx.x >> 8;

    size_t off0 = ((size_t)(2 * pb) * H_CH + (size_t)h) * LL;
    const float* u0 = u + off0;
    const float* u1 = u0 + (size_t)H_CH * LL;

    #pragma unroll
    for (int it = 0; it < 8; ++it) {
        int i = tid + it * 512;
        A[SW8(i)] = make_float2(u0[i], u1[i]);
    }
    __syncthreads();

    fft8stages<-1>(A, Bf, tid);                 // forward FFT of packed rows

    const float2* Kh = g_Khat + ((size_t)h << 12);
    #pragma unroll
    for (int it = 0; it < 8; ++it) {
        int i = tid + it * 512;
        A[SW8(i)] = cmul(A[SW8(i)], Kh[i]);     // spectral multiply (incl. 1/L)
    }
    __syncthreads();

    fft8stages<1>(A, Bf, tid);                  // inverse FFT (no extra scale)

    float* y0 = y + off0;
    float* y1 = y0 + (size_t)H_CH * LL;
    #pragma unroll
    for (int it = 0; it < 8; ++it) {
        int i = tid + it * 512;
        float2 z = A[SW8(i)];
        y0[i] = z.x;
        y1[i] = z.y;
    }
}

// ---------------------------------------------------------------------------
extern "C" void kernel_launch(void* const* d_in, const int* in_sizes, int n_in,
                              void* d_out, int out_size) {
    (void)in_sizes; (void)n_in; (void)out_size;
    const float* u   = (const float*)d_in[0];
    const float* Lre = (const float*)d_in[1];
    const float* Lim = (const float*)d_in[2];
    const float* Pre = (const float*)d_in[3];
    const float* Pim = (const float*)d_in[4];
    const float* Bre = (const float*)d_in[5];
    const float* Bim = (const float*)d_in[6];
    const float* Cre = (const float*)d_in[7];
    const float* Cim = (const float*)d_in[8];
    const float* lst = (const float*)d_in[9];
    float* y = (float*)d_out;

    const int smem_bytes = 2 * NPAD * (int)sizeof(float2);  // 73728
    cudaFuncSetAttribute(fftconv, cudaFuncAttributeMaxDynamicSharedMemorySize, smem_bytes);

    kgen<<<H_CH * 8, 256>>>(Lre, Lim, Pre, Pim, Bre, Bim, Cre, Cim, lst);
    fftconv<<<(NBATCH / 2) * H_CH, 512, smem_bytes>>>(u, y);
}

// round 8
// speedup vs baseline: 1.6218x; 1.1711x over previous
#include <cuda_runtime.h>
#include <cstdint>

#define H_CH 256
#define NST  64
#define LL   4096
#define NBATCH 16

typedef unsigned long long ull;

// Scratch (device global: allocation-free rule)
__device__ float2 g_Khat[H_CH * LL];   // hermitian part of K, pre-scaled by 1/L

__device__ __forceinline__ float2 cmul(float2 a, float2 b) {
    return make_float2(a.x * b.x - a.y * b.y, a.x * b.y + a.y * b.x);
}
__device__ __forceinline__ float2 cadd(float2 a, float2 b) {
    return make_float2(a.x + b.x, a.y + b.y);
}
__device__ __forceinline__ float2 csub(float2 a, float2 b) {
    return make_float2(a.x - b.x, a.y - b.y);
}

// ---- packed f32x2 helpers ----
__device__ __forceinline__ ull pk(float lo, float hi) {
    ull r; asm("mov.b64 %0,{%1,%2};" : "=l"(r) : "f"(lo), "f"(hi)); return r;
}
__device__ __forceinline__ void upk(ull v, float& lo, float& hi) {
    asm("mov.b64 {%0,%1},%2;" : "=f"(lo), "=f"(hi) : "l"(v));
}
__device__ __forceinline__ ull fma2(ull a, ull b, ull c) {
    ull d; asm("fma.rn.f32x2 %0,%1,%2,%3;" : "=l"(d) : "l"(a), "l"(b), "l"(c)); return d;
}
__device__ __forceinline__ ull add2(ull a, ull b) {
    ull d; asm("add.rn.f32x2 %0,%1,%2;" : "=l"(d) : "l"(a), "l"(b)); return d;
}
__device__ __forceinline__ ull mul2(ull a, ull b) {
    ull d; asm("mul.rn.f32x2 %0,%1,%2;" : "=l"(d) : "l"(a), "l"(b)); return d;
}

// Correctly-rounded float sin/cos via double polynomial.
// Needed so 1+cos / 1-cos cancellation sites match the float32 reference bitwise.
// Valid for ang in [-2*pi, 0].
__device__ __forceinline__ void sincos_acc(float angf, float* s, float* c) {
    double x  = (double)angf;
    double kd = rint(x * 0.63661977236758134308);   // x / (pi/2)
    double r  = x - kd * 1.5707963267948966;
    r        -= kd * 6.123233995736766e-17;
    int q = (int)kd;
    double r2 = r * r;
    double sr = r * (1.0 + r2 * (-1.6666666666666666e-01 + r2 * (8.3333333333333332e-03
                 + r2 * (-1.9841269841269841e-04 + r2 * 2.7557319223985893e-06))));
    double cr = 1.0 + r2 * (-0.5 + r2 * (4.1666666666666664e-02
                 + r2 * (-1.3888888888888889e-03 + r2 * (2.4801587301587302e-05
                 - r2 * 2.7557319223985888e-07))));
    double ss, cc;
    switch (q & 3) {
        case 0:  ss =  sr; cc =  cr; break;
        case 1:  ss =  cr; cc = -sr; break;
        case 2:  ss = -sr; cc = -cr; break;
        default: ss = -cr; cc =  sr; break;
    }
    *s = (float)ss;
    *c = (float)cc;
}

// ---------------------------------------------------------------------------
// Kernel 1: S4 DPLR frequency-domain kernel + FUSED Hermitian part.
// (unchanged from R6 — known good, ~issue-bound)
// ---------------------------------------------------------------------------
__global__ __launch_bounds__(256)
void kgen(const float* __restrict__ Lre, const float* __restrict__ Lim,
          const float* __restrict__ Pre, const float* __restrict__ Pim,
          const float* __restrict__ Bre, const float* __restrict__ Bim,
          const float* __restrict__ Cre, const float* __restrict__ Cim,
          const float* __restrict__ lstep) {
    __shared__ float4 sA[NST];  // (-lam.re, -lam.im, |P|^2, |P|^2)
    __shared__ float4 sB[NST];  // (cb.x, cb.y, -cb.y, cb.x)   cb = conj(C)*B
    __shared__ float4 sC[NST];  // conj(C)*P
    __shared__ float4 sD[NST];  // conj(P)*B
    __shared__ float  s_tos;

    int h   = blockIdx.x >> 3;
    int seg = blockIdx.x & 7;
    int tid = threadIdx.x;

    if (tid < NST) {
        int idx = h * NST + tid;
        float lr = Lre[idx], li = Lim[idx];
        float pr = Pre[idx], pi = Pim[idx];
        float br = Bre[idx], bi = Bim[idx];
        float cr = Cre[idx], ci = Cim[idx];
        float cbx = cr * br + ci * bi, cby = cr * bi - ci * br;
        float cpx = cr * pr + ci * pi, cpy = cr * pi - ci * pr;
        float pbx = pr * br + pi * bi, pby = pr * bi - pi * br;
        float pp  = pr * pr + pi * pi;
        sA[tid] = make_float4(-lr, -li, pp, pp);
        sB[tid] = make_float4(cbx, cby, -cby, cbx);
        sC[tid] = make_float4(cpx, cpy, -cpy, cpx);
        sD[tid] = make_float4(pbx, pby, -pby, pbx);
    }
    if (tid == 0) s_tos = 2.0f / __expf(lstep[h]);
    __syncthreads();
    float tos = s_tos;

    const float neg2pi = (float)(-6.283185307179586);

    // mirror-pair l mapping: (gid, 4096-gid); gid==0 -> (0, 2048)
    int gid = seg * 256 + tid;          // 0..2047 per h
    int lv[2];
    lv[0] = gid;
    lv[1] = (gid == 0) ? 2048 : (LL - gid);
    bool selfm = (gid == 0);            // both bins self-mirrored

    float crv[2], civ[2];               // c = 2/(1+Omega)
    ull   gpk[2];
    #pragma unroll
    for (int ii = 0; ii < 2; ++ii) {
        int l = lv[ii];
        float ang = neg2pi * ((float)l * (1.0f / 4096.0f));
        float so, co;
        sincos_acc(ang, &so, &co);
        float opr = 1.0f + co, opi = so;     // 1 + Omega (exact subtraction sites)
        float omr = 1.0f - co, omi = -so;    // 1 - Omega
        float rinv = __fdividef(1.0f, opr * opr + opi * opi);
        crv[ii] =  2.0f * opr * rinv;
        civ[ii] = -2.0f * opi * rinv;
        float gr = tos * ((omr * opr + omi * opi) * rinv);
        float gi = tos * ((omi * opr - omr * opi) * rinv);
        gpk[ii] = pk(gr, gi);
    }

    ull a00[2] = {0ull, 0ull}, a01[2] = {0ull, 0ull};
    ull a10[2] = {0ull, 0ull}, a11[2] = {0ull, 0ull};

    #pragma unroll 8
    for (int n = 0; n < NST; ++n) {
        float4 fa = sA[n], fb = sB[n], fc = sC[n], fd = sD[n];
        ull nlam = pk(fa.x, fa.y);
        ull pp2  = pk(fa.z, fa.w);
        ull bxy  = pk(fb.x, fb.y), bzw = pk(fb.z, fb.w);
        ull cxy  = pk(fc.x, fc.y), czw = pk(fc.z, fc.w);
        ull dxy  = pk(fd.x, fd.y), dzw = pk(fd.z, fd.w);
        #pragma unroll
        for (int ii = 0; ii < 2; ++ii) {
            ull d = add2(gpk[ii], nlam);         // g - lambda
            float dr, di; upk(d, dr, di);
            float inv = __fdividef(1.0f, fmaf(dr, dr, di * di));
            ull iriq = mul2(d, pk(inv, -inv));   // (ir, iq) = 1/(g-lam)
            float ir, iq; upk(iriq, ir, iq);
            ull irir = pk(ir, ir), iqiq = pk(iq, iq);
            a00[ii] = fma2(bxy, irir, a00[ii]); a00[ii] = fma2(bzw, iqiq, a00[ii]);
            a01[ii] = fma2(cxy, irir, a01[ii]); a01[ii] = fma2(czw, iqiq, a01[ii]);
            a10[ii] = fma2(dxy, irir, a10[ii]); a10[ii] = fma2(dzw, iqiq, a10[ii]);
            a11[ii] = fma2(pp2, iriq, a11[ii]);
        }
    }

    float2 kout[2];
    #pragma unroll
    for (int ii = 0; ii < 2; ++ii) {
        float a00r, a00i, a01r, a01i, a10r, a10i, a11r, a11i;
        upk(a00[ii], a00r, a00i); upk(a01[ii], a01r, a01i);
        upk(a10[ii], a10r, a10i); upk(a11[ii], a11r, a11i);
        // K = c * (k00 - k01 * k10 / (1 + k11))
        float tr = 1.0f + a11r, ti = a11i;
        float tinv = __fdividef(1.0f, tr * tr + ti * ti);
        float mr = a01r * a10r - a01i * a10i;
        float mi = a01r * a10i + a01i * a10r;
        float qr = (mr * tr + mi * ti) * tinv;
        float qi = (mi * tr - mr * ti) * tinv;
        float kr = a00r - qr, ki = a00i - qi;
        float cr_ = crv[ii], ci_ = civ[ii];
        kout[ii] = make_float2(cr_ * kr - ci_ * ki, cr_ * ki + ci_ * kr);
    }

    // Fused Hermitian part: Khat[l] = (K[l] + conj(K[-l])) * 0.5/L
    const float sc = 0.5f / 4096.0f;
    float2* Kh = g_Khat + ((size_t)h << 12);
    if (selfm) {
        Kh[lv[0]] = make_float2(2.0f * kout[0].x * sc, 0.0f);
        Kh[lv[1]] = make_float2(2.0f * kout[1].x * sc, 0.0f);
    } else {
        Kh[lv[0]] = make_float2((kout[0].x + kout[1].x) * sc,
                                (kout[0].y - kout[1].y) * sc);
        Kh[lv[1]] = make_float2((kout[1].x + kout[0].x) * sc,
                                (kout[1].y - kout[0].y) * sc);
    }
}

// ---------------------------------------------------------------------------
// Kernel 2: packed FFT convolution, radix-8 Stockham (4096 = 8^4).
// Register-fused ends: gmem->fwd0 in regs; fwd3+Khat+inv0 in regs;
// inv3->gmem in regs. Only 6 smem write+read rounds total (was 10).
// ---------------------------------------------------------------------------
#define SW8(i) ((i) + ((i) >> 3))   // pad swizzle for radix-8 access patterns
#define NPAD 4608                   // 4096 + 512

template <int DIR>
__device__ __forceinline__ void dft8(const float2* x, float2* out) {
    const float D = (float)DIR;
    float2 t0 = cadd(x[0], x[4]), t1 = csub(x[0], x[4]);
    float2 t2 = cadd(x[2], x[6]);
    float2 d26 = csub(x[2], x[6]);
    float2 t3 = make_float2(-D * d26.y, D * d26.x);
    float2 e0 = cadd(t0, t2), e1 = cadd(t1, t3);
    float2 e2 = csub(t0, t2), e3 = csub(t1, t3);

    float2 u0 = cadd(x[1], x[5]), u1 = csub(x[1], x[5]);
    float2 u2 = cadd(x[3], x[7]);
    float2 d37 = csub(x[3], x[7]);
    float2 u3 = make_float2(-D * d37.y, D * d37.x);
    float2 o0 = cadd(u0, u2), o1 = cadd(u1, u3);
    float2 o2 = csub(u0, u2), o3 = csub(u1, u3);

    const float C8 = 0.70710678118654752f;
    float2 q1 = make_float2(C8 * (o1.x - D * o1.y), C8 * (D * o1.x + o1.y));
    float2 q2 = make_float2(-D * o2.y, D * o2.x);
    float2 q3 = make_float2(C8 * (-o3.x - D * o3.y), C8 * (D * o3.x - o3.y));

    out[0] = cadd(e0, o0); out[4] = csub(e0, o0);
    out[1] = cadd(e1, q1); out[5] = csub(e1, q1);
    out[2] = cadd(e2, q2); out[6] = csub(e2, q2);
    out[3] = cadd(e3, q3); out[7] = csub(e3, q3);
}

template <int DIR, int K>
__device__ __forceinline__ void twiddle8(float2* out, int p) {
    if (K < 3) {
        const float base = (float)DIR * 6.2831853071795864f / (float)(4096 >> (3 * K));
        float sn, cs;
        __sincosf(base * (float)p, &sn, &cs);
        float2 w1 = make_float2(cs, sn);
        float2 w2 = cmul(w1, w1);
        float2 w3 = cmul(w2, w1);
        float2 w4 = cmul(w2, w2);
        float2 w5 = cmul(w3, w2);
        float2 w6 = cmul(w3, w3);
        float2 w7 = cmul(w4, w3);
        out[1] = cmul(out[1], w1); out[2] = cmul(out[2], w2);
        out[3] = cmul(out[3], w3); out[4] = cmul(out[4], w4);
        out[5] = cmul(out[5], w5); out[6] = cmul(out[6], w6);
        out[7] = cmul(out[7], w7);
    }
}

// middle stage: smem -> smem
template <int DIR, int K>
__device__ __forceinline__ void stage_smem(const float2* X, float2* Y, int j) {
    float2 x[8];
    #pragma unroll
    for (int r = 0; r < 8; ++r) x[r] = X[SW8(j + 512 * r)];
    float2 out[8];
    dft8<DIR>(x, out);
    twiddle8<DIR, K>(out, j >> (3 * K));
    const int s = 1 << (3 * K);
    int p = j >> (3 * K), q = j & (s - 1);
    int wb = q + 8 * s * p;
    #pragma unroll
    for (int r = 0; r < 8; ++r) Y[SW8(wb + s * r)] = out[r];
}

__global__ __launch_bounds__(512, 2)
void fftconv(const float* __restrict__ u, float* __restrict__ y) {
    extern __shared__ float2 smem[];
    float2* B0 = smem;
    float2* B1 = smem + NPAD;
    int j  = threadIdx.x;
    int h  = blockIdx.x & 255;
    int pb = blockIdx.x >> 8;

    size_t off0 = ((size_t)(2 * pb) * H_CH + (size_t)h) * LL;
    const float* u0 = u + off0;
    const float* u1 = u0 + (size_t)H_CH * LL;

    // fused: gmem load + forward stage 0 (regs) -> smem
    {
        float2 x[8], out[8];
        #pragma unroll
        for (int r = 0; r < 8; ++r) {
            int i = j + 512 * r;
            x[r] = make_float2(u0[i], u1[i]);
        }
        dft8<-1>(x, out);
        twiddle8<-1, 0>(out, j);
        #pragma unroll
        for (int r = 0; r < 8; ++r) B0[SW8(8 * j + r)] = out[r];
    }
    __syncthreads();
    stage_smem<-1, 1>(B0, B1, j); __syncthreads();
    stage_smem<-1, 2>(B1, B0, j); __syncthreads();

    // fused: forward stage 3 (natural order out) + Khat multiply + inverse
    // stage 0 (all in regs) -> smem
    {
        float2 x[8], f[8], out[8];
        #pragma unroll
        for (int r = 0; r < 8; ++r) x[r] = B0[SW8(j + 512 * r)];
        dft8<-1>(x, f);                       // k=3: no twiddle
        const float2* Kh = g_Khat + ((size_t)h << 12);
        #pragma unroll
        for (int r = 0; r < 8; ++r) f[r] = cmul(f[r], Kh[j + 512 * r]);
        dft8<1>(f, out);
        twiddle8<1, 0>(out, j);
        #pragma unroll
        for (int r = 0; r < 8; ++r) B1[SW8(8 * j + r)] = out[r];
    }
    __syncthreads();
    stage_smem<1, 1>(B1, B0, j); __syncthreads();
    stage_smem<1, 2>(B0, B1, j); __syncthreads();

    // fused: inverse stage 3 (regs) -> gmem (natural order, coalesced)
    {
        float2 x[8], out[8];
        #pragma unroll
        for (int r = 0; r < 8; ++r) x[r] = B1[SW8(j + 512 * r)];
        dft8<1>(x, out);                      // k=3: no twiddle
        float* y0 = y + off0;
        float* y1 = y0 + (size_t)H_CH * LL;
        #pragma unroll
        for (int r = 0; r < 8; ++r) {
            int i = j + 512 * r;
            y0[i] = out[r].x;
            y1[i] = out[r].y;
        }
    }
}

// ---------------------------------------------------------------------------
extern "C" void kernel_launch(void* const* d_in, const int* in_sizes, int n_in,
                              void* d_out, int out_size) {
    (void)in_sizes; (void)n_in; (void)out_size;
    const float* u   = (const float*)d_in[0];
    const float* Lre = (const float*)d_in[1];
    const float* Lim = (const float*)d_in[2];
    const float* Pre = (const float*)d_in[3];
    const float* Pim = (const float*)d_in[4];
    const float* Bre = (const float*)d_in[5];
    const float* Bim = (const float*)d_in[6];
    const float* Cre = (const float*)d_in[7];
    const float* Cim = (const float*)d_in[8];
    const float* lst = (const float*)d_in[9];
    float* y = (float*)d_out;

    const int smem_bytes = 2 * NPAD * (int)sizeof(float2);  // 73728
    cudaFuncSetAttribute(fftconv, cudaFuncAttributeMaxDynamicSharedMemorySize, smem_bytes);

    kgen<<<H_CH * 8, 256>>>(Lre, Lim, Pre, Pim, Bre, Bim, Cre, Cim, lst);
    fftconv<<<(NBATCH / 2) * H_CH, 512, smem_bytes>>>(u, y);
}

// round 9
// speedup vs baseline: 1.6414x; 1.0121x over previous
#include <cuda_runtime.h>
#include <cstdint>

#define H_CH 256
#define NST  64
#define LL   4096
#define NBATCH 16

typedef unsigned long long ull;

// Scratch (device global: allocation-free rule)
__device__ float2 g_Khat[H_CH * LL];   // hermitian part of K, pre-scaled by 1/L

__device__ __forceinline__ float2 cmul(float2 a, float2 b) {
    return make_float2(a.x * b.x - a.y * b.y, a.x * b.y + a.y * b.x);
}
__device__ __forceinline__ float2 cadd(float2 a, float2 b) {
    return make_float2(a.x + b.x, a.y + b.y);
}
__device__ __forceinline__ float2 csub(float2 a, float2 b) {
    return make_float2(a.x - b.x, a.y - b.y);
}

// ---- packed f32x2 helpers ----
__device__ __forceinline__ ull pk(float lo, float hi) {
    ull r; asm("mov.b64 %0,{%1,%2};" : "=l"(r) : "f"(lo), "f"(hi)); return r;
}
__device__ __forceinline__ void upk(ull v, float& lo, float& hi) {
    asm("mov.b64 {%0,%1},%2;" : "=f"(lo), "=f"(hi) : "l"(v));
}
__device__ __forceinline__ ull fma2(ull a, ull b, ull c) {
    ull d; asm("fma.rn.f32x2 %0,%1,%2,%3;" : "=l"(d) : "l"(a), "l"(b), "l"(c)); return d;
}
__device__ __forceinline__ ull add2(ull a, ull b) {
    ull d; asm("add.rn.f32x2 %0,%1,%2;" : "=l"(d) : "l"(a), "l"(b)); return d;
}
__device__ __forceinline__ ull mul2(ull a, ull b) {
    ull d; asm("mul.rn.f32x2 %0,%1,%2;" : "=l"(d) : "l"(a), "l"(b)); return d;
}

// Correctly-rounded float sin/cos via double polynomial.
// Needed so 1+cos / 1-cos cancellation sites match the float32 reference bitwise.
// Valid for ang in [-2*pi, 0].
__device__ __forceinline__ void sincos_acc(float angf, float* s, float* c) {
    double x  = (double)angf;
    double kd = rint(x * 0.63661977236758134308);   // x / (pi/2)
    double r  = x - kd * 1.5707963267948966;
    r        -= kd * 6.123233995736766e-17;
    int q = (int)kd;
    double r2 = r * r;
    double sr = r * (1.0 + r2 * (-1.6666666666666666e-01 + r2 * (8.3333333333333332e-03
                 + r2 * (-1.9841269841269841e-04 + r2 * 2.7557319223985893e-06))));
    double cr = 1.0 + r2 * (-0.5 + r2 * (4.1666666666666664e-02
                 + r2 * (-1.3888888888888889e-03 + r2 * (2.4801587301587302e-05
                 - r2 * 2.7557319223985888e-07))));
    double ss, cc;
    switch (q & 3) {
        case 0:  ss =  sr; cc =  cr; break;
        case 1:  ss =  cr; cc = -sr; break;
        case 2:  ss = -sr; cc = -cr; break;
        default: ss = -cr; cc =  sr; break;
    }
    *s = (float)ss;
    *c = (float)cc;
}

// ---------------------------------------------------------------------------
// Kernel 1: S4 DPLR frequency-domain kernel + FUSED Hermitian part.
// Mirror-pair (gid, 4096-gid) per thread. Inner loop uses a single packed
// multiplier w = (p, q) = d * inv (where 1/d = p - i*q) against PRE-BROADCAST
// shared tables (v.x,v.x) / (v.y,v.y), eliminating per-iteration broadcast
// MOVs entirely:
//   accA += w * (v.x, v.x)   ;  accB += w * (v.y, v.y)
//   sum  = (accA.lo + accB.hi) + i*(accB.lo - accA.hi)
// ---------------------------------------------------------------------------
__global__ __launch_bounds__(256)
void kgen(const float* __restrict__ Lre, const float* __restrict__ Lim,
          const float* __restrict__ Pre, const float* __restrict__ Pim,
          const float* __restrict__ Bre, const float* __restrict__ Bim,
          const float* __restrict__ Cre, const float* __restrict__ Cim,
          const float* __restrict__ lstep) {
    __shared__ float4 sA[NST];  // (-lam.re, -lam.im, pp, pp)       pp = |P|^2
    __shared__ float4 sB[NST];  // (cb.x, cb.x, cb.y, cb.y)   cb = conj(C)*B
    __shared__ float4 sC[NST];  // (cp.x, cp.x, cp.y, cp.y)   cp = conj(C)*P
    __shared__ float4 sD[NST];  // (pb.x, pb.x, pb.y, pb.y)   pb = conj(P)*B
    __shared__ float  s_tos;

    int h   = blockIdx.x >> 3;
    int seg = blockIdx.x & 7;
    int tid = threadIdx.x;

    if (tid < NST) {
        int idx = h * NST + tid;
        float lr = Lre[idx], li = Lim[idx];
        float pr = Pre[idx], pi = Pim[idx];
        float br = Bre[idx], bi = Bim[idx];
        float cr = Cre[idx], ci = Cim[idx];
        float cbx = cr * br + ci * bi, cby = cr * bi - ci * br;
        float cpx = cr * pr + ci * pi, cpy = cr * pi - ci * pr;
        float pbx = pr * br + pi * bi, pby = pr * bi - pi * br;
        float pp  = pr * pr + pi * pi;
        sA[tid] = make_float4(-lr, -li, pp, pp);
        sB[tid] = make_float4(cbx, cbx, cby, cby);
        sC[tid] = make_float4(cpx, cpx, cpy, cpy);
        sD[tid] = make_float4(pbx, pbx, pby, pby);
    }
    if (tid == 0) s_tos = 2.0f / __expf(lstep[h]);
    __syncthreads();
    float tos = s_tos;

    const float neg2pi = (float)(-6.283185307179586);

    // mirror-pair l mapping: (gid, 4096-gid); gid==0 -> (0, 2048)
    int gid = seg * 256 + tid;          // 0..2047 per h
    int lv[2];
    lv[0] = gid;
    lv[1] = (gid == 0) ? 2048 : (LL - gid);
    bool selfm = (gid == 0);            // both bins self-mirrored

    float crv[2], civ[2];               // c = 2/(1+Omega)
    ull   gpk[2];
    #pragma unroll
    for (int ii = 0; ii < 2; ++ii) {
        int l = lv[ii];
        float ang = neg2pi * ((float)l * (1.0f / 4096.0f));
        float so, co;
        sincos_acc(ang, &so, &co);
        float opr = 1.0f + co, opi = so;     // 1 + Omega (exact subtraction sites)
        float omr = 1.0f - co, omi = -so;    // 1 - Omega
        float rinv = __fdividef(1.0f, opr * opr + opi * opi);
        crv[ii] =  2.0f * opr * rinv;
        civ[ii] = -2.0f * opi * rinv;
        float gr = tos * ((omr * opr + omi * opi) * rinv);
        float gi = tos * ((omi * opr - omr * opi) * rinv);
        gpk[ii] = pk(gr, gi);
    }

    // packed accumulators: per l, per sum: A (x-table) and B (y-table)
    ull aA0[2] = {0,0}, aB0[2] = {0,0};   // k00
    ull aA1[2] = {0,0}, aB1[2] = {0,0};   // k01
    ull aA2[2] = {0,0}, aB2[2] = {0,0};   // k10
    ull a11[2] = {0,0};                   // k11 (pp,pp)*w

    #pragma unroll 8
    for (int n = 0; n < NST; ++n) {
        float4 fa = sA[n], fb = sB[n], fc = sC[n], fd = sD[n];
        ull nlam = pk(fa.x, fa.y);
        ull pp2  = pk(fa.z, fa.w);
        ull bx   = pk(fb.x, fb.y), by = pk(fb.z, fb.w);
        ull cx   = pk(fc.x, fc.y), cy = pk(fc.z, fc.w);
        ull dx   = pk(fd.x, fd.y), dy = pk(fd.z, fd.w);
        #pragma unroll
        for (int ii = 0; ii < 2; ++ii) {
            ull d = add2(gpk[ii], nlam);         // d = g - lambda  (dr, di)
            ull sq = mul2(d, d);                 // (dr^2, di^2)
            float s0, s1; upk(sq, s0, s1);
            float inv = __fdividef(1.0f, s0 + s1);
            ull w = mul2(d, pk(inv, inv));       // w = (p, q); 1/d = p - i*q
            aA0[ii] = fma2(bx, w, aA0[ii]);
            aB0[ii] = fma2(by, w, aB0[ii]);
            aA1[ii] = fma2(cx, w, aA1[ii]);
            aB1[ii] = fma2(cy, w, aB1[ii]);
            aA2[ii] = fma2(dx, w, aA2[ii]);
            aB2[ii] = fma2(dy, w, aB2[ii]);
            a11[ii] = fma2(pp2, w, a11[ii]);
        }
    }

    float2 kout[2];
    #pragma unroll
    for (int ii = 0; ii < 2; ++ii) {
        float xA, xB, yA, yB;
        // k00
        upk(aA0[ii], xA, xB); upk(aB0[ii], yA, yB);
        float a00r = xA + yB, a00i = yA - xB;
        // k01
        upk(aA1[ii], xA, xB); upk(aB1[ii], yA, yB);
        float a01r = xA + yB, a01i = yA - xB;
        // k10
        upk(aA2[ii], xA, xB); upk(aB2[ii], yA, yB);
        float a10r = xA + yB, a10i = yA - xB;
        // k11 = (acc.lo, -acc.hi)
        upk(a11[ii], xA, xB);
        float a11r = xA, a11i = -xB;

        // K = c * (k00 - k01 * k10 / (1 + k11))
        float tr = 1.0f + a11r, ti = a11i;
        float tinv = __fdividef(1.0f, tr * tr + ti * ti);
        float mr = a01r * a10r - a01i * a10i;
        float mi = a01r * a10i + a01i * a10r;
        float qr = (mr * tr + mi * ti) * tinv;
        float qi = (mi * tr - mr * ti) * tinv;
        float kr = a00r - qr, ki = a00i - qi;
        float cr_ = crv[ii], ci_ = civ[ii];
        kout[ii] = make_float2(cr_ * kr - ci_ * ki, cr_ * ki + ci_ * kr);
    }

    // Fused Hermitian part: Khat[l] = (K[l] + conj(K[-l])) * 0.5/L
    const float sc = 0.5f / 4096.0f;
    float2* Kh = g_Khat + ((size_t)h << 12);
    if (selfm) {
        Kh[lv[0]] = make_float2(2.0f * kout[0].x * sc, 0.0f);
        Kh[lv[1]] = make_float2(2.0f * kout[1].x * sc, 0.0f);
    } else {
        Kh[lv[0]] = make_float2((kout[0].x + kout[1].x) * sc,
                                (kout[0].y - kout[1].y) * sc);
        Kh[lv[1]] = make_float2((kout[1].x + kout[0].x) * sc,
                                (kout[1].y - kout[0].y) * sc);
    }
}

// ---------------------------------------------------------------------------
// Kernel 2: packed FFT convolution, radix-8 Stockham (4096 = 8^4).
// Register-fused ends: gmem->fwd0 in regs; fwd3+Khat+inv0 in regs;
// inv3->gmem in regs. 6 smem write+read rounds total.  (unchanged from R8)
// ---------------------------------------------------------------------------
#define SW8(i) ((i) + ((i) >> 3))   // pad swizzle for radix-8 access patterns
#define NPAD 4608                   // 4096 + 512

template <int DIR>
__device__ __forceinline__ void dft8(const float2* x, float2* out) {
    const float D = (float)DIR;
    float2 t0 = cadd(x[0], x[4]), t1 = csub(x[0], x[4]);
    float2 t2 = cadd(x[2], x[6]);
    float2 d26 = csub(x[2], x[6]);
    float2 t3 = make_float2(-D * d26.y, D * d26.x);
    float2 e0 = cadd(t0, t2), e1 = cadd(t1, t3);
    float2 e2 = csub(t0, t2), e3 = csub(t1, t3);

    float2 u0 = cadd(x[1], x[5]), u1 = csub(x[1], x[5]);
    float2 u2 = cadd(x[3], x[7]);
    float2 d37 = csub(x[3], x[7]);
    float2 u3 = make_float2(-D * d37.y, D * d37.x);
    float2 o0 = cadd(u0, u2), o1 = cadd(u1, u3);
    float2 o2 = csub(u0, u2), o3 = csub(u1, u3);

    const float C8 = 0.70710678118654752f;
    float2 q1 = make_float2(C8 * (o1.x - D * o1.y), C8 * (D * o1.x + o1.y));
    float2 q2 = make_float2(-D * o2.y, D * o2.x);
    float2 q3 = make_float2(C8 * (-o3.x - D * o3.y), C8 * (D * o3.x - o3.y));

    out[0] = cadd(e0, o0); out[4] = csub(e0, o0);
    out[1] = cadd(e1, q1); out[5] = csub(e1, q1);
    out[2] = cadd(e2, q2); out[6] = csub(e2, q2);
    out[3] = cadd(e3, q3); out[7] = csub(e3, q3);
}

template <int DIR, int K>
__device__ __forceinline__ void twiddle8(float2* out, int p) {
    if (K < 3) {
        const float base = (float)DIR * 6.2831853071795864f / (float)(4096 >> (3 * K));
        float sn, cs;
        __sincosf(base * (float)p, &sn, &cs);
        float2 w1 = make_float2(cs, sn);
        float2 w2 = cmul(w1, w1);
        float2 w3 = cmul(w2, w1);
        float2 w4 = cmul(w2, w2);
        float2 w5 = cmul(w3, w2);
        float2 w6 = cmul(w3, w3);
        float2 w7 = cmul(w4, w3);
        out[1] = cmul(out[1], w1); out[2] = cmul(out[2], w2);
        out[3] = cmul(out[3], w3); out[4] = cmul(out[4], w4);
        out[5] = cmul(out[5], w5); out[6] = cmul(out[6], w6);
        out[7] = cmul(out[7], w7);
    }
}

// middle stage: smem -> smem
template <int DIR, int K>
__device__ __forceinline__ void stage_smem(const float2* X, float2* Y, int j) {
    float2 x[8];
    #pragma unroll
    for (int r = 0; r < 8; ++r) x[r] = X[SW8(j + 512 * r)];
    float2 out[8];
    dft8<DIR>(x, out);
    twiddle8<DIR, K>(out, j >> (3 * K));
    const int s = 1 << (3 * K);
    int p = j >> (3 * K), q = j & (s - 1);
    int wb = q + 8 * s * p;
    #pragma unroll
    for (int r = 0; r < 8; ++r) Y[SW8(wb + s * r)] = out[r];
}

__global__ __launch_bounds__(512, 2)
void fftconv(const float* __restrict__ u, float* __restrict__ y) {
    extern __shared__ float2 smem[];
    float2* B0 = smem;
    float2* B1 = smem + NPAD;
    int j  = threadIdx.x;
    int h  = blockIdx.x & 255;
    int pb = blockIdx.x >> 8;

    size_t off0 = ((size_t)(2 * pb) * H_CH + (size_t)h) * LL;
    const float* u0 = u + off0;
    const float* u1 = u0 + (size_t)H_CH * LL;

    // fused: gmem load + forward stage 0 (regs) -> smem
    {
        float2 x[8], out[8];
        #pragma unroll
        for (int r = 0; r < 8; ++r) {
            int i = j + 512 * r;
            x[r] = make_float2(u0[i], u1[i]);
        }
        dft8<-1>(x, out);
        twiddle8<-1, 0>(out, j);
        #pragma unroll
        for (int r = 0; r < 8; ++r) B0[SW8(8 * j + r)] = out[r];
    }
    __syncthreads();
    stage_smem<-1, 1>(B0, B1, j); __syncthreads();
    stage_smem<-1, 2>(B1, B0, j); __syncthreads();

    // fused: forward stage 3 (natural order out) + Khat multiply + inverse
    // stage 0 (all in regs) -> smem
    {
        float2 x[8], f[8], out[8];
        #pragma unroll
        for (int r = 0; r < 8; ++r) x[r] = B0[SW8(j + 512 * r)];
        dft8<-1>(x, f);                       // k=3: no twiddle
        const float2* Kh = g_Khat + ((size_t)h << 12);
        #pragma unroll
        for (int r = 0; r < 8; ++r) f[r] = cmul(f[r], Kh[j + 512 * r]);
        dft8<1>(f, out);
        twiddle8<1, 0>(out, j);
        #pragma unroll
        for (int r = 0; r < 8; ++r) B1[SW8(8 * j + r)] = out[r];
    }
    __syncthreads();
    stage_smem<1, 1>(B1, B0, j); __syncthreads();
    stage_smem<1, 2>(B0, B1, j); __syncthreads();

    // fused: inverse stage 3 (regs) -> gmem (natural order, coalesced)
    {
        float2 x[8], out[8];
        #pragma unroll
        for (int r = 0; r < 8; ++r) x[r] = B1[SW8(j + 512 * r)];
        dft8<1>(x, out);                      // k=3: no twiddle
        float* y0 = y + off0;
        float* y1 = y0 + (size_t)H_CH * LL;
        #pragma unroll
        for (int r = 0; r < 8; ++r) {
            int i = j + 512 * r;
            y0[i] = out[r].x;
            y1[i] = out[r].y;
        }
    }
}

// ---------------------------------------------------------------------------
extern "C" void kernel_launch(void* const* d_in, const int* in_sizes, int n_in,
                              void* d_out, int out_size) {
    (void)in_sizes; (void)n_in; (void)out_size;
    const float* u   = (const float*)d_in[0];
    const float* Lre = (const float*)d_in[1];
    const float* Lim = (const float*)d_in[2];
    const float* Pre = (const float*)d_in[3];
    const float* Pim = (const float*)d_in[4];
    const float* Bre = (const float*)d_in[5];
    const float* Bim = (const float*)d_in[6];
    const float* Cre = (const float*)d_in[7];
    const float* Cim = (const float*)d_in[8];
    const float* lst = (const float*)d_in[9];
    float* y = (float*)d_out;

    const int smem_bytes = 2 * NPAD * (int)sizeof(float2);  // 73728
    cudaFuncSetAttribute(fftconv, cudaFuncAttributeMaxDynamicSharedMemorySize, smem_bytes);

    kgen<<<H_CH * 8, 256>>>(Lre, Lim, Pre, Pim, Bre, Bim, Cre, Cim, lst);
    fftconv<<<(NBATCH / 2) * H_CH, 512, smem_bytes>>>(u, y);
}